// round 1
// baseline (speedup 1.0000x reference)
#include <cuda_runtime.h>

// Problem constants (ChamferDistance_755914244601): B=4, N=M=8192, 3D points.
#define BB 4
#define NN 8192
#define MM 8192
#define MSPLIT 4      // split of the scanned dimension across blocks
#define TM 256        // smem tile of scanned points (== TPB)
#define KN 2          // register-blocked owned points per thread
#define TPB 256

// Scratch partials: [B, NA, MSPLIT]
__device__ float g_part1[BB * NN * MSPLIT];
__device__ float g_part2[BB * MM * MSPLIT];

// One direction of chamfer distance.
//  a    : thread-owned points  [B, NA, 3]
//  bpts : scanned points       [B, NB, 3]
// writes min_j( ||a_i - b_j||^2 ) partial over this block's split into g_part{1,2}.
__global__ void __launch_bounds__(TPB)
chamfer_dir_kernel(const float* __restrict__ a,
                   const float* __restrict__ bpts,
                   int NA, int NB, int which)
{
    __shared__ float4 s[TM];   // (-2x, -2y, -2z, x^2+y^2+z^2) per scanned point

    float* __restrict__ part = which ? g_part2 : g_part1;

    const int b     = blockIdx.z;
    const int split = blockIdx.y;
    const int n0    = blockIdx.x * (TPB * KN) + threadIdx.x;

    float px[KN], py[KN], pz[KN], sq[KN];
    float mnA[KN], mnB[KN];
#pragma unroll
    for (int k = 0; k < KN; k++) {
        const int n = n0 + k * TPB;
        const float* p = a + ((size_t)b * NA + n) * 3;
        px[k] = p[0]; py[k] = p[1]; pz[k] = p[2];
        sq[k] = px[k]*px[k] + py[k]*py[k] + pz[k]*pz[k];
        mnA[k] = 3.4e38f;
        mnB[k] = 3.4e38f;
    }

    const int mbeg = split * (NB / MSPLIT);
    const int mend = mbeg + (NB / MSPLIT);

    for (int mt = mbeg; mt < mend; mt += TM) {
        __syncthreads();
        {
            // one scanned point per thread (TPB == TM)
            const int j = threadIdx.x;
            const float* q = bpts + ((size_t)b * NB + mt + j) * 3;
            const float x = q[0], y = q[1], z = q[2];
            s[j] = make_float4(-2.0f * x, -2.0f * y, -2.0f * z,
                               x * x + y * y + z * z);
        }
        __syncthreads();

#pragma unroll 8
        for (int j = 0; j < TM; j += 2) {
            const float4 p0 = s[j];
            const float4 p1 = s[j + 1];
#pragma unroll
            for (int k = 0; k < KN; k++) {
                // v = sq2 - 2*dot  (3 FFMA), row-constant sq1 added after the min
                float v0 = fmaf(p0.x, px[k], fmaf(p0.y, py[k], fmaf(p0.z, pz[k], p0.w)));
                float v1 = fmaf(p1.x, px[k], fmaf(p1.y, py[k], fmaf(p1.z, pz[k], p1.w)));
                mnA[k] = fminf(mnA[k], v0);   // two accumulators break the min
                mnB[k] = fminf(mnB[k], v1);   // dependency chain
            }
        }
    }

#pragma unroll
    for (int k = 0; k < KN; k++) {
        const int n = n0 + k * TPB;
        part[((size_t)b * NA + n) * MSPLIT + split] =
            fminf(mnA[k], mnB[k]) + sq[k];
    }
}

// Combine the MSPLIT partials and write the final output buffer:
// out[0 .. B*N)       = d1
// out[B*N .. B*N+B*M) = d2
__global__ void chamfer_reduce_kernel(float* __restrict__ out)
{
    const int i = blockIdx.x * blockDim.x + threadIdx.x;
    const int total1 = BB * NN;
    const int total  = BB * NN + BB * MM;
    if (i >= total) return;

    const float* part;
    int idx;
    if (i < total1) { part = g_part1; idx = i; }
    else            { part = g_part2; idx = i - total1; }

    float m = part[(size_t)idx * MSPLIT + 0];
#pragma unroll
    for (int sp = 1; sp < MSPLIT; sp++)
        m = fminf(m, part[(size_t)idx * MSPLIT + sp]);
    out[i] = m;
}

extern "C" void kernel_launch(void* const* d_in, const int* in_sizes, int n_in,
                              void* d_out, int out_size)
{
    const float* xyz1 = (const float*)d_in[0];   // [B, N, 3]
    const float* xyz2 = (const float*)d_in[1];   // [B, M, 3]
    float* out = (float*)d_out;                  // [B*N + B*M]

    dim3 grid1(NN / (TPB * KN), MSPLIT, BB);
    dim3 grid2(MM / (TPB * KN), MSPLIT, BB);

    // d1: owned = xyz1, scanned = xyz2
    chamfer_dir_kernel<<<grid1, TPB>>>(xyz1, xyz2, NN, MM, 0);
    // d2: owned = xyz2, scanned = xyz1
    chamfer_dir_kernel<<<grid2, TPB>>>(xyz2, xyz1, MM, NN, 1);

    const int total = BB * NN + BB * MM;
    chamfer_reduce_kernel<<<(total + 255) / 256, 256>>>(out);
}